// round 11
// baseline (speedup 1.0000x reference)
#include <cuda_runtime.h>
#include <cuda_bf16.h>
#include <cstdint>

// Batched NT-GEMM: C[b,i,j] = sum_d A[b,i,d] * B[b,j,d]
// B=8, M=N=4096, K=128, fp32 in/out.
//
// Split-precision bf16 path: x = hi + lo (bf16 each);
// C ~= Ahi*Bhi + Ahi*Blo + Alo*Bhi via mma.sync.m16n8k16.bf16 (2x tf32 rate).
// Phase 1: prepass -> fragment-major hi/lo scratch.
// Phase 2: 128x128-tile GEMM, 256 thr, 2 CTA/SM, cp.async double buffer.

#define BATCH 8
#define MDIM 4096
#define NDIM 4096
#define KDIM 128

#define TILE_M 128
#define TILE_N 128
#define NCHUNKS 4          // K chunks of 32 (2 k16-steps each)

// Fragment-major scratch (u32 units):
// Ahi/Alo: [b][M128(32)][step(8)][mt(8)][lane(32)][r(4)]   8192 u32 per (b,M)
// Bhi/Blo: [b][N128(32)][step(8)][nt(16)][lane(32)][r(2)]  8192 u32 per (b,N)
__device__ uint32_t g_Ahi[(size_t)BATCH * 32 * 8192];
__device__ uint32_t g_Alo[(size_t)BATCH * 32 * 8192];
__device__ uint32_t g_Bhi[(size_t)BATCH * 32 * 8192];
__device__ uint32_t g_Blo[(size_t)BATCH * 32 * 8192];

// Smem per buffer (u32): [Ahi 2048][Alo 2048][Bhi 2048][Blo 2048] = 32KB
#define BUF_U32 8192
#define SMEM_BYTES (2 * BUF_U32 * 4)    // 64 KB

__device__ __forceinline__ uint32_t smem_u32(const void* p) {
    uint32_t a;
    asm("{ .reg .u64 t; cvta.to.shared.u64 t, %1; cvt.u32.u64 %0, t; }"
        : "=r"(a) : "l"(p));
    return a;
}

__device__ __forceinline__ void split2(float x0, float x1,
                                       uint32_t& hi, uint32_t& lo) {
    __nv_bfloat16 h0 = __float2bfloat16_rn(x0);
    __nv_bfloat16 h1 = __float2bfloat16_rn(x1);
    __nv_bfloat16 l0 = __float2bfloat16_rn(x0 - __bfloat162float(h0));
    __nv_bfloat16 l1 = __float2bfloat16_rn(x1 - __bfloat162float(h1));
    hi = ((uint32_t)__bfloat16_as_ushort(h1) << 16) | __bfloat16_as_ushort(h0);
    lo = ((uint32_t)__bfloat16_as_ushort(l1) << 16) | __bfloat16_as_ushort(l0);
}

// ---------------- Prepass A: one thread per (b,M,step,mt,lane) ----------------
__global__ __launch_bounds__(256)
void prep_a_kernel(const float* __restrict__ A) {
    const int id   = blockIdx.x * 256 + threadIdx.x;   // 0 .. 2^19-1
    const int lane = id & 31;
    const int mt   = (id >> 5) & 7;
    const int step = (id >> 8) & 7;
    const int M    = (id >> 11) & 31;
    const int b    = id >> 16;

    const int g  = lane >> 2;
    const int tt = lane & 3;
    const int m0 = M * 128 + mt * 16 + g;
    const int ks = step * 16 + tt * 2;

    const float* src = A + ((size_t)b * MDIM + m0) * KDIM;
    // r0: (g, ks..ks+1)  r1: (g+8, ks..ks+1)  r2: (g, ks+8..9)  r3: (g+8, ks+8..9)
    uint4 hi, lo;
    split2(src[ks],             src[ks + 1],             hi.x, lo.x);
    split2(src[8 * KDIM + ks],  src[8 * KDIM + ks + 1],  hi.y, lo.y);
    split2(src[ks + 8],         src[ks + 9],             hi.z, lo.z);
    split2(src[8 * KDIM + ks + 8], src[8 * KDIM + ks + 9], hi.w, lo.w);

    *reinterpret_cast<uint4*>(g_Ahi + (size_t)id * 4) = hi;
    *reinterpret_cast<uint4*>(g_Alo + (size_t)id * 4) = lo;
}

// ---------------- Prepass B: one thread per (b,N,step,nt,lane) ----------------
__global__ __launch_bounds__(256)
void prep_b_kernel(const float* __restrict__ B) {
    const int id   = blockIdx.x * 256 + threadIdx.x;   // 0 .. 2^20-1
    const int lane = id & 31;
    const int nt   = (id >> 5) & 15;
    const int step = (id >> 9) & 7;
    const int N    = (id >> 12) & 31;
    const int b    = id >> 17;

    const int g  = lane >> 2;
    const int tt = lane & 3;
    const int n0 = N * 128 + nt * 8 + g;
    const int ks = step * 16 + tt * 2;

    const float* src = B + ((size_t)b * NDIM + n0) * KDIM;
    uint2 hi, lo;
    split2(src[ks],     src[ks + 1], hi.x, lo.x);
    split2(src[ks + 8], src[ks + 9], hi.y, lo.y);

    *reinterpret_cast<uint2*>(g_Bhi + (size_t)id * 2) = hi;
    *reinterpret_cast<uint2*>(g_Blo + (size_t)id * 2) = lo;
}

// ---------------- Main GEMM ----------------
__global__ __launch_bounds__(256, 2)
void bmm_bf16x2_kernel(float* __restrict__ C) {
    extern __shared__ uint32_t sm[];
    const uint32_t smem_base = smem_u32(sm);

    const int tid  = threadIdx.x;
    const int lane = tid & 31;
    const int wid  = tid >> 5;
    const int g    = lane >> 2;
    const int tt   = lane & 3;

    const int b  = blockIdx.z;
    const int by = blockIdx.y;
    const int bx = blockIdx.x;

    const uint32_t* srcAhi = g_Ahi + (size_t)(b * 32 + by) * 8192;
    const uint32_t* srcAlo = g_Alo + (size_t)(b * 32 + by) * 8192;
    const uint32_t* srcBhi = g_Bhi + (size_t)(b * 32 + bx) * 8192;
    const uint32_t* srcBlo = g_Blo + (size_t)(b * 32 + bx) * 8192;
    float* Cb = C + (size_t)b * MDIM * NDIM;

    const int mband = wid >> 2;         // 0..1
    const int nband = wid & 3;          // 0..3

    float acc[4][4][4];
    #pragma unroll
    for (int i = 0; i < 4; i++)
        #pragma unroll
        for (int j = 0; j < 4; j++)
            #pragma unroll
            for (int r = 0; r < 4; r++)
                acc[i][j][r] = 0.0f;

    // Prefetch chunk c (2 k16-steps = 2048 u32 per array) into buffer buf.
    auto prefetch = [&](int buf, int c) {
        const uint32_t d0 = smem_base + (uint32_t)buf * (BUF_U32 * 4);
        const uint32_t coff = (uint32_t)c * 2048;
        #pragma unroll
        for (int i = 0; i < 2; i++) {
            const int o = tid + i * 256;           // float4 index 0..511
            asm volatile("cp.async.cg.shared.global [%0], [%1], 16;"
                         :: "r"(d0 + (uint32_t)o * 16),
                            "l"(srcAhi + coff + o * 4));
            asm volatile("cp.async.cg.shared.global [%0], [%1], 16;"
                         :: "r"(d0 + 8192 + (uint32_t)o * 16),
                            "l"(srcAlo + coff + o * 4));
            asm volatile("cp.async.cg.shared.global [%0], [%1], 16;"
                         :: "r"(d0 + 16384 + (uint32_t)o * 16),
                            "l"(srcBhi + coff + o * 4));
            asm volatile("cp.async.cg.shared.global [%0], [%1], 16;"
                         :: "r"(d0 + 24576 + (uint32_t)o * 16),
                            "l"(srcBlo + coff + o * 4));
        }
    };

    prefetch(0, 0);
    asm volatile("cp.async.commit_group;" ::: "memory");
    prefetch(1, 1);
    asm volatile("cp.async.commit_group;" ::: "memory");

    #pragma unroll
    for (int ch = 0; ch < NCHUNKS; ch++) {
        if (ch < NCHUNKS - 1)
            asm volatile("cp.async.wait_group 1;" ::: "memory");
        else
            asm volatile("cp.async.wait_group 0;" ::: "memory");
        __syncthreads();

        const uint32_t* Ahi_s = sm + (ch & 1) * BUF_U32;   // [s2][mt8][lane][4]
        const uint32_t* Alo_s = Ahi_s + 2048;
        const uint32_t* Bhi_s = Ahi_s + 4096;              // [s2][nt16][lane][2]
        const uint32_t* Blo_s = Ahi_s + 6144;

        #pragma unroll
        for (int s = 0; s < 2; s++) {
            uint32_t ah[4][4], al[4][4];
            #pragma unroll
            for (int i = 0; i < 4; i++) {
                const uint32_t* p =
                    Ahi_s + ((s * 8 + mband * 4 + i) * 32 + lane) * 4;
                asm volatile("ld.shared.v4.b32 {%0,%1,%2,%3}, [%4];"
                             : "=r"(ah[i][0]), "=r"(ah[i][1]),
                               "=r"(ah[i][2]), "=r"(ah[i][3])
                             : "l"(p));
                const uint32_t* q =
                    Alo_s + ((s * 8 + mband * 4 + i) * 32 + lane) * 4;
                asm volatile("ld.shared.v4.b32 {%0,%1,%2,%3}, [%4];"
                             : "=r"(al[i][0]), "=r"(al[i][1]),
                               "=r"(al[i][2]), "=r"(al[i][3])
                             : "l"(q));
            }
            #pragma unroll
            for (int j = 0; j < 4; j++) {
                uint32_t bh[2], bl[2];
                const uint32_t* p =
                    Bhi_s + ((s * 16 + nband * 4 + j) * 32 + lane) * 2;
                asm volatile("ld.shared.v2.b32 {%0,%1}, [%2];"
                             : "=r"(bh[0]), "=r"(bh[1]) : "l"(p));
                const uint32_t* q =
                    Blo_s + ((s * 16 + nband * 4 + j) * 32 + lane) * 2;
                asm volatile("ld.shared.v2.b32 {%0,%1}, [%2];"
                             : "=r"(bl[0]), "=r"(bl[1]) : "l"(q));

                #pragma unroll
                for (int i = 0; i < 4; i++) {
                    asm volatile(
                        "mma.sync.aligned.m16n8k16.row.col.f32.bf16.bf16.f32 "
                        "{%0,%1,%2,%3}, {%4,%5,%6,%7}, {%8,%9}, {%0,%1,%2,%3};"
                        : "+f"(acc[i][j][0]), "+f"(acc[i][j][1]),
                          "+f"(acc[i][j][2]), "+f"(acc[i][j][3])
                        : "r"(ah[i][0]), "r"(ah[i][1]),
                          "r"(ah[i][2]), "r"(ah[i][3]),
                          "r"(bh[0]), "r"(bh[1]));
                    asm volatile(
                        "mma.sync.aligned.m16n8k16.row.col.f32.bf16.bf16.f32 "
                        "{%0,%1,%2,%3}, {%4,%5,%6,%7}, {%8,%9}, {%0,%1,%2,%3};"
                        : "+f"(acc[i][j][0]), "+f"(acc[i][j][1]),
                          "+f"(acc[i][j][2]), "+f"(acc[i][j][3])
                        : "r"(ah[i][0]), "r"(ah[i][1]),
                          "r"(ah[i][2]), "r"(ah[i][3]),
                          "r"(bl[0]), "r"(bl[1]));
                    asm volatile(
                        "mma.sync.aligned.m16n8k16.row.col.f32.bf16.bf16.f32 "
                        "{%0,%1,%2,%3}, {%4,%5,%6,%7}, {%8,%9}, {%0,%1,%2,%3};"
                        : "+f"(acc[i][j][0]), "+f"(acc[i][j][1]),
                          "+f"(acc[i][j][2]), "+f"(acc[i][j][3])
                        : "r"(al[i][0]), "r"(al[i][1]),
                          "r"(al[i][2]), "r"(al[i][3]),
                          "r"(bh[0]), "r"(bh[1]));
                }
            }
        }

        if (ch + 2 < NCHUNKS) {
            __syncthreads();
            prefetch(ch & 1, ch + 2);
            asm volatile("cp.async.commit_group;" ::: "memory");
        }
    }

    // Epilogue: c0,c1 -> (g, 2tt..2tt+1); c2,c3 -> (g+8, ...)
    const int mBase = by * TILE_M;
    const int nBase = bx * TILE_N;
    #pragma unroll
    for (int i = 0; i < 4; i++) {
        const int row0 = mBase + mband * 64 + i * 16 + g;
        #pragma unroll
        for (int j = 0; j < 4; j++) {
            const int col = nBase + nband * 32 + j * 8 + tt * 2;
            float2 lo2 = make_float2(acc[i][j][0], acc[i][j][1]);
            float2 hi2 = make_float2(acc[i][j][2], acc[i][j][3]);
            *reinterpret_cast<float2*>(Cb + (size_t)row0 * NDIM + col) = lo2;
            *reinterpret_cast<float2*>(Cb + (size_t)(row0 + 8) * NDIM + col) = hi2;
        }
    }
}

extern "C" void kernel_launch(void* const* d_in, const int* in_sizes, int n_in,
                              void* d_out, int out_size) {
    const float* A = (const float*)d_in[0];
    const float* B = (const float*)d_in[1];
    float* C = (float*)d_out;

    cudaFuncSetAttribute(bmm_bf16x2_kernel,
                         cudaFuncAttributeMaxDynamicSharedMemorySize, SMEM_BYTES);

    prep_a_kernel<<<2048, 256>>>(A);     // 2^19 threads
    prep_b_kernel<<<4096, 256>>>(B);     // 2^20 threads

    dim3 grid(NDIM / TILE_N, MDIM / TILE_M, BATCH);  // 32 x 32 x 8
    bmm_bf16x2_kernel<<<grid, 256, SMEM_BYTES>>>(C);
}

// round 12
// speedup vs baseline: 1.2304x; 1.2304x over previous
#include <cuda_runtime.h>
#include <cstdint>

// Batched NT-GEMM: C[b,i,j] = sum_d A[b,i,d] * B[b,j,d]
// B=8, M=N=4096, K=128, fp32 in/out.
//
// tf32 mma.sync.m16n8k8 path (MAC-optimal legacy format on sm_103 base target).
// Phase 1: prepass converts A,B to tf32 (RNA) into fragment-major scratch.
// Phase 2: 128x128-tile GEMM, 256 thr, 2 CTA/SM, 3-stage cp.async pipeline
// (96KB smem) with prefetch hoisted to chunk top; 4 bar.sync per CTA.

#define BATCH 8
#define MDIM 4096
#define NDIM 4096
#define KDIM 128

#define TILE_M 128
#define TILE_N 128
#define NCHUNKS 4          // K chunks of 32 (4 kt-groups of 8)
#define NSTAGES 3

// Fragment-major scratch:
// Atf: [b][M128(32)][kt(16)][mt(8)][lane(32)][r(4)]   (16.8 MB)
// Btf: [b][N128(32)][kt(16)][nt(16)][lane(32)][r(2)]  (16.8 MB)
__device__ float g_Atf[(size_t)BATCH * MDIM * KDIM];
__device__ float g_Btf[(size_t)BATCH * NDIM * KDIM];

// Smem per stage: A 4096 floats [kt4][mt8][lane32][r4], B 4096 floats
// [kt4][nt16][lane32][r2].  3 stages x 32KB = 96KB.
#define BUF_FLOATS 8192
#define SMEM_BYTES (NSTAGES * BUF_FLOATS * 4)

__device__ __forceinline__ float f2tf32f(float f) {
    uint32_t u;
    asm("cvt.rna.tf32.f32 %0, %1;" : "=r"(u) : "f"(f));
    return __uint_as_float(u);
}

__device__ __forceinline__ uint32_t smem_u32(const void* p) {
    uint32_t a;
    asm("{ .reg .u64 t; cvta.to.shared.u64 t, %1; cvt.u32.u64 %0, t; }"
        : "=r"(a) : "l"(p));
    return a;
}

// ---------------- Prepass ----------------
__global__ __launch_bounds__(256)
void prep_a_kernel(const float* __restrict__ A) {
    const int id   = blockIdx.x * 256 + threadIdx.x;   // 0 .. 2^20-1
    const int lane = id & 31;
    const int mt   = (id >> 5) & 7;
    const int kt   = (id >> 8) & 15;
    const int M    = (id >> 12) & 31;
    const int b    = id >> 17;

    const int g  = lane >> 2;
    const int tt = lane & 3;
    const int m0 = M * 128 + mt * 16 + g;
    const int k0 = kt * 8 + tt;

    const float* src = A + ((size_t)b * MDIM + m0) * KDIM;
    float4 v;
    v.x = f2tf32f(src[k0]);
    v.y = f2tf32f(src[8 * KDIM + k0]);
    v.z = f2tf32f(src[k0 + 4]);
    v.w = f2tf32f(src[8 * KDIM + k0 + 4]);
    *reinterpret_cast<float4*>(g_Atf + (size_t)id * 4) = v;
}

__global__ __launch_bounds__(256)
void prep_b_kernel(const float* __restrict__ B) {
    const int id   = blockIdx.x * 256 + threadIdx.x;   // 0 .. 2^21-1
    const int lane = id & 31;
    const int nt   = (id >> 5) & 15;
    const int kt   = (id >> 9) & 15;
    const int N    = (id >> 13) & 31;
    const int b    = id >> 18;

    const int g  = lane >> 2;
    const int tt = lane & 3;
    const int n0 = N * 128 + nt * 8 + g;
    const int k0 = kt * 8 + tt;

    const float* src = B + ((size_t)b * NDIM + n0) * KDIM;
    float2 v;
    v.x = f2tf32f(src[k0]);
    v.y = f2tf32f(src[k0 + 4]);
    *reinterpret_cast<float2*>(g_Btf + (size_t)id * 2) = v;
}

// ---------------- Main GEMM ----------------
__global__ __launch_bounds__(256, 2)
void bmm_tf32_frag_kernel(float* __restrict__ C) {
    extern __shared__ float sm[];
    const uint32_t smem_base = smem_u32(sm);

    const int tid  = threadIdx.x;
    const int lane = tid & 31;
    const int wid  = tid >> 5;
    const int g    = lane >> 2;
    const int tt   = lane & 3;

    const int b  = blockIdx.z;
    const int by = blockIdx.y;          // M128 tile
    const int bx = blockIdx.x;          // N128 tile

    const float* srcA = g_Atf + (size_t)((b * 32 + by) * 16) * 1024;
    const float* srcB = g_Btf + (size_t)((b * 32 + bx) * 16) * 1024;
    float* Cb = C + (size_t)b * MDIM * NDIM;

    const int mband = wid >> 2;         // 0..1
    const int nband = wid & 3;          // 0..3

    float acc[4][4][4];
    #pragma unroll
    for (int i = 0; i < 4; i++)
        #pragma unroll
        for (int j = 0; j < 4; j++)
            #pragma unroll
            for (int r = 0; r < 4; r++)
                acc[i][j][r] = 0.0f;

    auto prefetch = [&](int buf, int c) {
        const float* ca = srcA + c * 4096;
        const float* cb = srcB + c * 4096;
        const uint32_t da = smem_base + (uint32_t)buf * (BUF_FLOATS * 4);
        const uint32_t db = da + 16384;
        #pragma unroll
        for (int i = 0; i < 4; i++) {
            const int o = tid + i * 256;      // 16B chunk index
            asm volatile("cp.async.cg.shared.global [%0], [%1], 16;"
                         :: "r"(da + (uint32_t)o * 16), "l"(ca + o * 4));
            asm volatile("cp.async.cg.shared.global [%0], [%1], 16;"
                         :: "r"(db + (uint32_t)o * 16), "l"(cb + o * 4));
        }
    };

    prefetch(0, 0);
    asm volatile("cp.async.commit_group;" ::: "memory");
    prefetch(1, 1);
    asm volatile("cp.async.commit_group;" ::: "memory");

    #pragma unroll
    for (int ch = 0; ch < NCHUNKS; ch++) {
        if (ch < NCHUNKS - 1)
            asm volatile("cp.async.wait_group 1;" ::: "memory");
        else
            asm volatile("cp.async.wait_group 0;" ::: "memory");
        __syncthreads();

        // Hoisted prefetch: chunk ch+2 into stage (ch+2)%3.  That stage last
        // held chunk ch-1, which every warp finished before this barrier.
        if (ch + 2 < NCHUNKS) {
            prefetch((ch + 2) % NSTAGES, ch + 2);
            asm volatile("cp.async.commit_group;" ::: "memory");
        }

        const float* As = sm + (ch % NSTAGES) * BUF_FLOATS; // [kt][mt8][lane][4]
        const float* Bs = As + 4096;                        // [kt][nt16][lane][2]

        #pragma unroll
        for (int kt = 0; kt < 4; kt++) {
            uint32_t a[4][4], bf[4][2];
            #pragma unroll
            for (int i = 0; i < 4; i++) {
                const float* p = As + ((kt * 8 + mband * 4 + i) * 32 + lane) * 4;
                asm volatile("ld.shared.v4.b32 {%0,%1,%2,%3}, [%4];"
                             : "=r"(a[i][0]), "=r"(a[i][1]),
                               "=r"(a[i][2]), "=r"(a[i][3])
                             : "l"(p));
            }
            #pragma unroll
            for (int j = 0; j < 4; j++) {
                const float* p = Bs + ((kt * 16 + nband * 4 + j) * 32 + lane) * 2;
                asm volatile("ld.shared.v2.b32 {%0,%1}, [%2];"
                             : "=r"(bf[j][0]), "=r"(bf[j][1])
                             : "l"(p));
            }
            #pragma unroll
            for (int i = 0; i < 4; i++)
                #pragma unroll
                for (int j = 0; j < 4; j++) {
                    asm volatile(
                        "mma.sync.aligned.m16n8k8.row.col.f32.tf32.tf32.f32 "
                        "{%0,%1,%2,%3}, {%4,%5,%6,%7}, {%8,%9}, {%0,%1,%2,%3};"
                        : "+f"(acc[i][j][0]), "+f"(acc[i][j][1]),
                          "+f"(acc[i][j][2]), "+f"(acc[i][j][3])
                        : "r"(a[i][0]), "r"(a[i][1]),
                          "r"(a[i][2]), "r"(a[i][3]),
                          "r"(bf[j][0]), "r"(bf[j][1]));
                }
        }
    }

    // Epilogue
    const int mBase = by * TILE_M;
    const int nBase = bx * TILE_N;
    #pragma unroll
    for (int i = 0; i < 4; i++) {
        const int row0 = mBase + mband * 64 + i * 16 + g;
        #pragma unroll
        for (int j = 0; j < 4; j++) {
            const int col = nBase + nband * 32 + j * 8 + tt * 2;
            float2 lo = make_float2(acc[i][j][0], acc[i][j][1]);
            float2 hi = make_float2(acc[i][j][2], acc[i][j][3]);
            *reinterpret_cast<float2*>(Cb + (size_t)row0 * NDIM + col) = lo;
            *reinterpret_cast<float2*>(Cb + (size_t)(row0 + 8) * NDIM + col) = hi;
        }
    }
}

extern "C" void kernel_launch(void* const* d_in, const int* in_sizes, int n_in,
                              void* d_out, int out_size) {
    const float* A = (const float*)d_in[0];
    const float* B = (const float*)d_in[1];
    float* C = (float*)d_out;

    cudaFuncSetAttribute(bmm_tf32_frag_kernel,
                         cudaFuncAttributeMaxDynamicSharedMemorySize, SMEM_BYTES);

    prep_a_kernel<<<4096, 256>>>(A);     // 2^20 threads
    prep_b_kernel<<<8192, 256>>>(B);     // 2^21 threads

    dim3 grid(NDIM / TILE_N, MDIM / TILE_M, BATCH);  // 32 x 32 x 8
    bmm_tf32_frag_kernel<<<grid, 256, SMEM_BYTES>>>(C);
}